// round 2
// baseline (speedup 1.0000x reference)
#include <cuda_runtime.h>
#include <cuda_bf16.h>
#include <cstdint>

#define CHARS   10000
#define HIDDEN  1024
#define OUTPUT  100
#define BATCH   4096
#define MAXLEN  2048

#define K_PAD   10240
#define NPAD    128
#define NSLICE  4
#define K_SLICE (K_PAD / NSLICE)      // 2560
#define NCHUNK_MAIN (K_SLICE / 64)    // 40
#define NCHUNK_WC   (HIDDEN / 64)     // 16

// ---------------- device scratch (static; allocations are banned) --------
__device__ __nv_bfloat16 g_hist[(size_t)BATCH * K_PAD];    // 84 MB
__device__ __nv_bfloat16 g_w1h[(size_t)HIDDEN * K_PAD];    // 21 MB
__device__ __nv_bfloat16 g_w1l[(size_t)HIDDEN * K_PAD];    // 21 MB
__device__ __nv_bfloat16 g_w2h[(size_t)NPAD * HIDDEN];
__device__ __nv_bfloat16 g_w2l[(size_t)NPAD * HIDDEN];
__device__ __nv_bfloat16 g_wchi[(size_t)NPAD * K_PAD];     // 2.6 MB
__device__ __nv_bfloat16 g_wclo[(size_t)NPAD * K_PAD];     // 2.6 MB
__device__ float         g_part[(size_t)NSLICE * BATCH * NPAD]; // 8.4 MB
__device__ float         g_bc[OUTPUT];

// ---------------- PTX helpers (portable sm_80-class only) ----------------
__device__ __forceinline__ uint32_t smem_u32(const void* p) {
    uint32_t a;
    asm("{ .reg .u64 t; cvta.to.shared.u64 t, %1; cvt.u32.u64 %0, t; }"
        : "=r"(a) : "l"(p));
    return a;
}

__device__ __forceinline__ void cp16(uint32_t s, const void* g) {
    asm volatile("cp.async.cg.shared.global [%0], [%1], 16;" :: "r"(s), "l"(g));
}
#define CP_COMMIT() asm volatile("cp.async.commit_group;" ::: "memory")
#define CP_WAIT1()  asm volatile("cp.async.wait_group 1;"  ::: "memory")

__device__ __forceinline__ void ldsm4(uint32_t* r, uint32_t a) {
    asm volatile("ldmatrix.sync.aligned.m8n8.x4.shared.b16 {%0,%1,%2,%3}, [%4];"
        : "=r"(r[0]), "=r"(r[1]), "=r"(r[2]), "=r"(r[3]) : "r"(a));
}
__device__ __forceinline__ void ldsm4t(uint32_t* r, uint32_t a) {
    asm volatile("ldmatrix.sync.aligned.m8n8.x4.trans.shared.b16 {%0,%1,%2,%3}, [%4];"
        : "=r"(r[0]), "=r"(r[1]), "=r"(r[2]), "=r"(r[3]) : "r"(a));
}

// D(16x8,f32) += A(16x16,bf16) @ B(16x8,bf16)
__device__ __forceinline__ void mma16816(float* c, const uint32_t* a, const uint32_t* b) {
    asm volatile(
        "mma.sync.aligned.m16n8k16.row.col.f32.bf16.bf16.f32 "
        "{%0,%1,%2,%3}, {%4,%5,%6,%7}, {%8,%9}, {%0,%1,%2,%3};"
        : "+f"(c[0]), "+f"(c[1]), "+f"(c[2]), "+f"(c[3])
        : "r"(a[0]), "r"(a[1]), "r"(a[2]), "r"(a[3]), "r"(b[0]), "r"(b[1]));
}

// smem pitches (bytes): 64-col bf16 tile rows padded +8 elems; 128-col +8
#define PA 144
#define PB 272

// ---------------- kernel 1: per-row histogram -> bf16 (exact) ------------
__global__ void __launch_bounds__(256) hist_kernel(const int* __restrict__ words) {
    __shared__ unsigned cnt[K_PAD];
    int b = blockIdx.x;
    for (int i = threadIdx.x; i < K_PAD; i += 256) cnt[i] = 0u;
    __syncthreads();
    const int* w = words + (size_t)b * MAXLEN;
    #pragma unroll 4
    for (int j = threadIdx.x; j < MAXLEN; j += 256) {
        unsigned c = (unsigned)w[j];
        if (c < CHARS) atomicAdd(&cnt[c], 1u);
    }
    __syncthreads();
    __nv_bfloat162* out = (__nv_bfloat162*)(g_hist + (size_t)b * K_PAD);
    for (int i = threadIdx.x; i < K_PAD / 2; i += 256) {
        __nv_bfloat162 v;
        v.x = __float2bfloat16_rn((float)cnt[2 * i]);
        v.y = __float2bfloat16_rn((float)cnt[2 * i + 1]);
        out[i] = v;
    }
}

// ---------------- kernel 2a: split W1 -> bf16 hi/lo, padded [h][K_PAD] ---
__global__ void __launch_bounds__(256) conv_w1(const float* __restrict__ W1) {
    unsigned i = blockIdx.x * 256u + threadIdx.x;   // pair index
    unsigned h = i / (K_PAD / 2);
    unsigned c = (i - h * (K_PAD / 2)) * 2u;
    float v0 = 0.f, v1 = 0.f;
    if (c < CHARS) {   // CHARS even -> pair never straddles the edge
        const float* p = W1 + (size_t)h * CHARS + c;
        v0 = p[0]; v1 = p[1];
    }
    __nv_bfloat16 h0 = __float2bfloat16_rn(v0);
    __nv_bfloat16 h1 = __float2bfloat16_rn(v1);
    __nv_bfloat16 l0 = __float2bfloat16_rn(v0 - __bfloat162float(h0));
    __nv_bfloat16 l1 = __float2bfloat16_rn(v1 - __bfloat162float(h1));
    ((__nv_bfloat162*)g_w1h)[i] = __nv_bfloat162(h0, h1);
    ((__nv_bfloat162*)g_w1l)[i] = __nv_bfloat162(l0, l1);
}

// ---------------- kernel 2b: split W2 -> bf16 hi/lo, padded [128][1024] --
__global__ void __launch_bounds__(256) conv_w2(const float* __restrict__ W2) {
    unsigned i = blockIdx.x * 256u + threadIdx.x;   // over 128*1024
    unsigned o = i >> 10, h = i & 1023u;
    float v = (o < OUTPUT) ? W2[(size_t)o * HIDDEN + h] : 0.f;
    __nv_bfloat16 hi = __float2bfloat16_rn(v);
    g_w2h[i] = hi;
    g_w2l[i] = __float2bfloat16_rn(v - __bfloat162float(hi));
}

// ---------------- kernel 3: bc = b2 + W2 @ b1 -----------------------------
__global__ void bc_kernel(const float* __restrict__ W2,
                          const float* __restrict__ b1,
                          const float* __restrict__ b2) {
    int o = threadIdx.x;
    if (o < OUTPUT) {
        float acc = b2[o];
        for (int h = 0; h < HIDDEN; h++) acc += W2[(size_t)o * HIDDEN + h] * b1[h];
        g_bc[o] = acc;
    }
}

// ---------------- kernel 4: Wc = W2 @ W1 (3-pass bf16 HMMA) --------------
// CTA: 128 o x 128 c, K = 1024 (h). grid = 80. 256 threads = 8 warps (4x2).
#define WC_AH 0
#define WC_AL 18432
#define WC_BH 36864
#define WC_BL (36864 + 17408)
#define WC_STG 71680

__global__ void __launch_bounds__(256) wc_gemm() {
    extern __shared__ char smn[];
    uint32_t sb = smem_u32(smn);
    const int tid = threadIdx.x, lid = tid & 31, wid = tid >> 5;
    const int wm = wid >> 1, wn = wid & 1, gid = lid >> 2, t4 = lid & 3;
    const int c0 = blockIdx.x * 128;

    // cp.async thread mapping
    const int arow = tid >> 1;                 // 0..127 (o)
    const int acol = (tid & 1) * 64;           // byte offset in 128B row
    const int brow = tid >> 2;                 // 0..63 (h)
    const int bcol = (tid & 3) * 64;           // byte offset in 256B row
    const char* gAh = (const char*)(g_w2h + (size_t)arow * HIDDEN);
    const char* gAl = (const char*)(g_w2l + (size_t)arow * HIDDEN);
    const char* gBh = (const char*)(g_w1h + (size_t)brow * K_PAD + c0);
    const char* gBl = (const char*)(g_w1l + (size_t)brow * K_PAD + c0);
    const uint32_t sAh = sb + WC_AH + arow * PA + acol;
    const uint32_t sAl = sb + WC_AL + arow * PA + acol;
    const uint32_t sBh = sb + WC_BH + brow * PB + bcol;
    const uint32_t sBl = sb + WC_BL + brow * PB + bcol;

    float acc[2][8][4];
    #pragma unroll
    for (int mb = 0; mb < 2; mb++)
        #pragma unroll
        for (int nf = 0; nf < 8; nf++)
            #pragma unroll
            for (int e = 0; e < 4; e++) acc[mb][nf][e] = 0.f;

    auto issue = [&](int it) {
        if (it < NCHUNK_WC) {
            uint32_t so = (it & 1) * WC_STG;
            size_t ka = (size_t)it * 128;             // A: +128B along k
            size_t kb = (size_t)it * 64 * K_PAD * 2;  // B: +64 h-rows
            #pragma unroll
            for (int i = 0; i < 4; i++) {
                cp16(sAh + so + i * 16, gAh + ka + acol + i * 16);
                cp16(sAl + so + i * 16, gAl + ka + acol + i * 16);
                cp16(sBh + so + i * 16, gBh + kb + bcol + i * 16);
                cp16(sBl + so + i * 16, gBl + kb + bcol + i * 16);
            }
        }
        CP_COMMIT();
    };

    issue(0); issue(1);
    for (int it = 0; it < NCHUNK_WC; ++it) {
        uint32_t st = sb + (it & 1) * WC_STG;
        CP_WAIT1();
        __syncthreads();
        #pragma unroll
        for (int ks = 0; ks < 4; ks++) {
            uint32_t ah[2][4], al[2][4], bh[16], bl[16];
            #pragma unroll
            for (int mb = 0; mb < 2; mb++) {
                uint32_t r = (wm * 32 + mb * 16 + (lid & 15));
                uint32_t ad = st + r * PA + ks * 32 + (lid >> 4) * 16;
                ldsm4(ah[mb], ad + WC_AH);
                ldsm4(al[mb], ad + WC_AL);
            }
            #pragma unroll
            for (int nq = 0; nq < 4; nq++) {
                // trans load: row = h, col = c
                uint32_t r = ks * 16 + ((lid >> 3) & 1) * 8 + (lid & 7);
                uint32_t cb = (wn * 64 + nq * 16) * 2 + ((lid >> 4) & 1) * 16;
                uint32_t ad = st + r * PB + cb;
                ldsm4t(&bh[nq * 4], ad + WC_BH);
                ldsm4t(&bl[nq * 4], ad + WC_BL);
            }
            #pragma unroll
            for (int mb = 0; mb < 2; mb++)
                #pragma unroll
                for (int nf = 0; nf < 8; nf++) {
                    mma16816(acc[mb][nf], ah[mb], &bh[nf * 2]);
                    mma16816(acc[mb][nf], al[mb], &bh[nf * 2]);
                    mma16816(acc[mb][nf], ah[mb], &bl[nf * 2]);
                }
        }
        __syncthreads();
        issue(it + 2);
    }

    // epilogue: split fp32 -> bf16 hi/lo, store [o][c]
    #pragma unroll
    for (int mb = 0; mb < 2; mb++)
        #pragma unroll
        for (int nf = 0; nf < 8; nf++) {
            int o = wm * 32 + mb * 16 + gid;
            int c = c0 + wn * 64 + nf * 8 + t4 * 2;
            #pragma unroll
            for (int half = 0; half < 2; half++) {
                float v0 = acc[mb][nf][half * 2 + 0];
                float v1 = acc[mb][nf][half * 2 + 1];
                __nv_bfloat16 h0 = __float2bfloat16_rn(v0);
                __nv_bfloat16 h1 = __float2bfloat16_rn(v1);
                __nv_bfloat16 l0 = __float2bfloat16_rn(v0 - __bfloat162float(h0));
                __nv_bfloat16 l1 = __float2bfloat16_rn(v1 - __bfloat162float(h1));
                size_t idx = (size_t)(o + half * 8) * K_PAD + c;
                *(__nv_bfloat162*)(g_wchi + idx) = __nv_bfloat162(h0, h1);
                *(__nv_bfloat162*)(g_wclo + idx) = __nv_bfloat162(l0, l1);
            }
        }
}

// ---------------- kernel 5: main GEMM  out_part = hist @ Wc^T ------------
// CTA: 128 m x 128 n, K-slice 2560. grid (32, NSLICE). 8 warps (4x2).
#define MG_A  0
#define MG_BH 18432
#define MG_BL 36864
#define MG_STG 55296

__global__ void __launch_bounds__(256) main_gemm() {
    extern __shared__ char smn[];
    uint32_t sb = smem_u32(smn);
    const int tid = threadIdx.x, lid = tid & 31, wid = tid >> 5;
    const int wm = wid >> 1, wn = wid & 1, gid = lid >> 2, t4 = lid & 3;
    const int m0 = blockIdx.x * 128;
    const int kbase = blockIdx.y * K_SLICE;

    const int arow = tid >> 1;
    const int acol = (tid & 1) * 64;
    const char* gA  = (const char*)(g_hist + (size_t)(m0 + arow) * K_PAD + kbase);
    const char* gBh = (const char*)(g_wchi + (size_t)arow * K_PAD + kbase);
    const char* gBl = (const char*)(g_wclo + (size_t)arow * K_PAD + kbase);
    const uint32_t sA  = sb + MG_A  + arow * PA + acol;
    const uint32_t sBh = sb + MG_BH + arow * PA + acol;
    const uint32_t sBl = sb + MG_BL + arow * PA + acol;

    float acc[2][8][4];
    #pragma unroll
    for (int mb = 0; mb < 2; mb++)
        #pragma unroll
        for (int nf = 0; nf < 8; nf++)
            #pragma unroll
            for (int e = 0; e < 4; e++) acc[mb][nf][e] = 0.f;

    auto issue = [&](int it) {
        if (it < NCHUNK_MAIN) {
            uint32_t so = (it & 1) * MG_STG;
            size_t ko = (size_t)it * 128;
            #pragma unroll
            for (int i = 0; i < 4; i++) {
                cp16(sA  + so + i * 16, gA  + ko + acol + i * 16);
                cp16(sBh + so + i * 16, gBh + ko + acol + i * 16);
                cp16(sBl + so + i * 16, gBl + ko + acol + i * 16);
            }
        }
        CP_COMMIT();
    };

    issue(0); issue(1);
    for (int it = 0; it < NCHUNK_MAIN; ++it) {
        uint32_t st = sb + (it & 1) * MG_STG;
        CP_WAIT1();
        __syncthreads();
        #pragma unroll
        for (int ks = 0; ks < 4; ks++) {
            uint32_t a[2][4], bh[16], bl[16];
            #pragma unroll
            for (int mb = 0; mb < 2; mb++) {
                uint32_t r = (wm * 32 + mb * 16 + (lid & 15));
                ldsm4(a[mb], st + MG_A + r * PA + ks * 32 + (lid >> 4) * 16);
            }
            #pragma unroll
            for (int nq = 0; nq < 4; nq++) {
                uint32_t r = wn * 64 + nq * 16 + ((lid >> 4) & 1) * 8 + (lid & 7);
                uint32_t ad = st + r * PA + ks * 32 + ((lid >> 3) & 1) * 16;
                ldsm4(&bh[nq * 4], ad + (MG_BH - MG_A));
                ldsm4(&bl[nq * 4], ad + (MG_BL - MG_A));
            }
            #pragma unroll
            for (int mb = 0; mb < 2; mb++)
                #pragma unroll
                for (int nf = 0; nf < 8; nf++) {
                    mma16816(acc[mb][nf], a[mb], &bh[nf * 2]);
                    mma16816(acc[mb][nf], a[mb], &bl[nf * 2]);
                }
        }
        __syncthreads();
        issue(it + 2);
    }

    // epilogue: fp32 partials
    float* base = g_part + (size_t)blockIdx.y * BATCH * NPAD;
    #pragma unroll
    for (int mb = 0; mb < 2; mb++)
        #pragma unroll
        for (int nf = 0; nf < 8; nf++) {
            int row = m0 + wm * 32 + mb * 16 + gid;
            int col = wn * 64 + nf * 8 + t4 * 2;
            *(float2*)(base + (size_t)row * NPAD + col) =
                make_float2(acc[mb][nf][0], acc[mb][nf][1]);
            *(float2*)(base + (size_t)(row + 8) * NPAD + col) =
                make_float2(acc[mb][nf][2], acc[mb][nf][3]);
        }
}

// ---------------- kernel 6: split-K reduce + bias ------------------------
__global__ void __launch_bounds__(256) reduce_kernel(float* __restrict__ out) {
    int i = blockIdx.x * 256 + threadIdx.x;   // BATCH*OUTPUT threads exactly
    int b = i / OUTPUT;
    int o = i - b * OUTPUT;
    float s = g_bc[o];
    #pragma unroll
    for (int sl = 0; sl < NSLICE; sl++)
        s += g_part[((size_t)sl * BATCH + b) * NPAD + o];
    out[i] = s;
}

// ---------------- launch ---------------------------------------------------
extern "C" void kernel_launch(void* const* d_in, const int* in_sizes, int n_in,
                              void* d_out, int out_size) {
    const int*   words = (const int*)  d_in[0];
    const float* W1    = (const float*)d_in[1];
    const float* b1    = (const float*)d_in[2];
    const float* W2    = (const float*)d_in[3];
    const float* b2    = (const float*)d_in[4];

    hist_kernel<<<BATCH, 256>>>(words);
    conv_w1<<<(HIDDEN * (K_PAD / 2)) / 256, 256>>>(W1);
    conv_w2<<<(NPAD * HIDDEN) / 256, 256>>>(W2);
    bc_kernel<<<1, 128>>>(W2, b1, b2);

    cudaFuncSetAttribute(wc_gemm, cudaFuncAttributeMaxDynamicSharedMemorySize, 2 * WC_STG);
    wc_gemm<<<K_PAD / 128, 256, 2 * WC_STG>>>();

    cudaFuncSetAttribute(main_gemm, cudaFuncAttributeMaxDynamicSharedMemorySize, 2 * MG_STG);
    main_gemm<<<dim3(K_PAD ? 32 : 32, NSLICE), 256, 2 * MG_STG>>>();

    reduce_kernel<<<(BATCH * OUTPUT) / 256, 256>>>((float*)d_out);
}

// round 3
// speedup vs baseline: 1.4586x; 1.4586x over previous
#include <cuda_runtime.h>
#include <cuda_bf16.h>
#include <cstdint>

#define CHARS   10000
#define HIDDEN  1024
#define OUTPUT  100
#define BATCH   4096
#define MAXLEN  2048

#define K_PAD   10240
#define NPAD    128
#define NSLICE  8
#define K_SLICE (K_PAD / NSLICE)      // 1280
#define NCHUNK_MAIN (K_SLICE / 64)    // 20
#define NCHUNK_WC   (HIDDEN / 64)     // 16

// ---------------- device scratch (static; allocations are banned) --------
__device__ __nv_bfloat16 g_hist[(size_t)BATCH * K_PAD];    // 84 MB
__device__ __nv_bfloat16 g_w2h[(size_t)NPAD * HIDDEN];
__device__ __nv_bfloat16 g_w2l[(size_t)NPAD * HIDDEN];
__device__ __nv_bfloat16 g_wchi[(size_t)NPAD * K_PAD];     // 2.6 MB
__device__ __nv_bfloat16 g_wclo[(size_t)NPAD * K_PAD];     // 2.6 MB
__device__ float         g_part[(size_t)NSLICE * BATCH * NPAD]; // 16.8 MB
__device__ float         g_bc[OUTPUT];

// ---------------- PTX helpers (portable sm_80-class only) ----------------
__device__ __forceinline__ uint32_t smem_u32(const void* p) {
    uint32_t a;
    asm("{ .reg .u64 t; cvta.to.shared.u64 t, %1; cvt.u32.u64 %0, t; }"
        : "=r"(a) : "l"(p));
    return a;
}

__device__ __forceinline__ void cp16(uint32_t s, const void* g) {
    asm volatile("cp.async.cg.shared.global [%0], [%1], 16;" :: "r"(s), "l"(g));
}
#define CP_COMMIT() asm volatile("cp.async.commit_group;" ::: "memory")
#define CP_WAIT1()  asm volatile("cp.async.wait_group 1;"  ::: "memory")

__device__ __forceinline__ void ldsm4(uint32_t* r, uint32_t a) {
    asm volatile("ldmatrix.sync.aligned.m8n8.x4.shared.b16 {%0,%1,%2,%3}, [%4];"
        : "=r"(r[0]), "=r"(r[1]), "=r"(r[2]), "=r"(r[3]) : "r"(a));
}
__device__ __forceinline__ void ldsm4t(uint32_t* r, uint32_t a) {
    asm volatile("ldmatrix.sync.aligned.m8n8.x4.trans.shared.b16 {%0,%1,%2,%3}, [%4];"
        : "=r"(r[0]), "=r"(r[1]), "=r"(r[2]), "=r"(r[3]) : "r"(a));
}

// D(16x8,f32) += A(16x16,bf16) @ B(16x8,bf16)
__device__ __forceinline__ void mma16816(float* c, const uint32_t* a, const uint32_t* b) {
    asm volatile(
        "mma.sync.aligned.m16n8k16.row.col.f32.bf16.bf16.f32 "
        "{%0,%1,%2,%3}, {%4,%5,%6,%7}, {%8,%9}, {%0,%1,%2,%3};"
        : "+f"(c[0]), "+f"(c[1]), "+f"(c[2]), "+f"(c[3])
        : "r"(a[0]), "r"(a[1]), "r"(a[2]), "r"(a[3]), "r"(b[0]), "r"(b[1]));
}

__device__ __forceinline__ void split2(float a, float b,
                                       __nv_bfloat162& hi, __nv_bfloat162& lo) {
    __nv_bfloat16 h0 = __float2bfloat16_rn(a);
    __nv_bfloat16 h1 = __float2bfloat16_rn(b);
    hi = __nv_bfloat162(h0, h1);
    lo = __nv_bfloat162(__float2bfloat16_rn(a - __bfloat162float(h0)),
                        __float2bfloat16_rn(b - __bfloat162float(h1)));
}

// smem pitches (bytes): 64-col bf16 rows padded +8 elems; 128-col +8
#define PA 144
#define PB 272

// ---------------- kernel 1: per-row histogram -> bf16 (exact) ------------
// packed u16 counters: word i holds chars 2i (lo) and 2i+1 (hi)
__global__ void __launch_bounds__(256) hist_kernel(const int* __restrict__ words) {
    __shared__ unsigned cnt[K_PAD / 2];
    int b = blockIdx.x;
    for (int i = threadIdx.x; i < K_PAD / 2; i += 256) cnt[i] = 0u;
    __syncthreads();
    const int* w = words + (size_t)b * MAXLEN;
    #pragma unroll 8
    for (int j = threadIdx.x; j < MAXLEN; j += 256) {
        unsigned c = (unsigned)w[j];
        atomicAdd(&cnt[c >> 1], 1u << ((c & 1u) * 16));
    }
    __syncthreads();
    __nv_bfloat162* out = (__nv_bfloat162*)(g_hist + (size_t)b * K_PAD);
    for (int i = threadIdx.x; i < K_PAD / 2; i += 256) {
        unsigned v = cnt[i];
        out[i] = __nv_bfloat162(__float2bfloat16_rn((float)(v & 0xFFFFu)),
                                __float2bfloat16_rn((float)(v >> 16)));
    }
}

// ---------------- kernel 2: split W2 -> bf16 hi/lo, padded [128][1024] ---
__global__ void __launch_bounds__(256) conv_w2(const float* __restrict__ W2) {
    unsigned i = blockIdx.x * 256u + threadIdx.x;   // over 128*1024
    unsigned o = i >> 10;
    float v = (o < OUTPUT) ? W2[(size_t)o * HIDDEN + (i & 1023u)] : 0.f;
    __nv_bfloat16 hi = __float2bfloat16_rn(v);
    g_w2h[i] = hi;
    g_w2l[i] = __float2bfloat16_rn(v - __bfloat162float(hi));
}

// ---------------- kernel 3: bc = b2 + W2 @ b1 (100 warps) -----------------
__global__ void __launch_bounds__(128) bc_kernel(const float* __restrict__ W2,
                                                 const float* __restrict__ b1,
                                                 const float* __restrict__ b2) {
    int o = blockIdx.x * 4 + (threadIdx.x >> 5);    // grid 25 x 128 -> 100 warps
    int lane = threadIdx.x & 31;
    const float* w = W2 + (size_t)o * HIDDEN;
    float s = 0.f;
    #pragma unroll 8
    for (int h = lane; h < HIDDEN; h += 32) s += w[h] * b1[h];
    #pragma unroll
    for (int off = 16; off; off >>= 1) s += __shfl_xor_sync(0xFFFFFFFFu, s, off);
    if (lane == 0) g_bc[o] = b2[o] + s;
}

// ---------------- kernel 4: Wc = W2 @ W1 (3-pass HMMA, fused W1 split) ---
// CTA: 128 o x 128 c, K = 1024 h. grid 80. 256 threads = 8 warps (4m x 2n).
// A = W2 hi/lo bf16 via cp.async; B = W1 fp32 via LDG -> reg convert -> STS.
#define WC_AH 0
#define WC_AL 18432
#define WC_BH 36864
#define WC_BL (36864 + 17408)
#define WC_STG 71680

__global__ void __launch_bounds__(256) wc_gemm(const float* __restrict__ W1) {
    extern __shared__ char smn[];
    uint32_t sb = smem_u32(smn);
    const int tid = threadIdx.x, lid = tid & 31, wid = tid >> 5;
    const int wm = wid >> 1, wn = wid & 1, gid = lid >> 2, t4 = lid & 3;
    const int c0 = blockIdx.x * 128;

    // A (W2 hi/lo) cp.async mapping: 128 rows x 128B
    const int arow = tid >> 1;
    const int acol = (tid & 1) * 64;                 // byte in 128B row
    const char* gAh = (const char*)(g_w2h + (size_t)arow * HIDDEN) + acol;
    const char* gAl = (const char*)(g_w2l + (size_t)arow * HIDDEN) + acol;
    const uint32_t sAh = sb + WC_AH + arow * PA + acol;
    const uint32_t sAl = sb + WC_AL + arow * PA + acol;

    // B (W1 fp32) LDG mapping: 64 h-rows x 512B; thread: row=tid>>2, 32 floats
    const int brow = tid >> 2;
    const int bcole = (tid & 3) * 32;                // element col base
    const uint32_t sB_hi = sb + WC_BH + brow * PB + bcole * 2;
    const uint32_t sB_lo = sb + WC_BL + brow * PB + bcole * 2;

    float4 rb[8];

    auto loadB = [&](int it) {
        const float* p = W1 + (size_t)(it * 64 + brow) * CHARS + c0 + bcole;
        #pragma unroll
        for (int i = 0; i < 8; i++) {
            int c = c0 + bcole + i * 4;
            rb[i] = (c < CHARS) ? *(const float4*)(p + i * 4)
                                : make_float4(0.f, 0.f, 0.f, 0.f);
        }
    };
    auto stsB = [&](uint32_t so) {
        #pragma unroll
        for (int j = 0; j < 4; j++) {               // 2 float4 -> 8 bf16 = 16B
            __nv_bfloat162 h0, l0, h1, l1, h2, l2, h3, l3;
            split2(rb[2*j].x,   rb[2*j].y,   h0, l0);
            split2(rb[2*j].z,   rb[2*j].w,   h1, l1);
            split2(rb[2*j+1].x, rb[2*j+1].y, h2, l2);
            split2(rb[2*j+1].z, rb[2*j+1].w, h3, l3);
            uint4 vh = make_uint4(*(uint32_t*)&h0, *(uint32_t*)&h1,
                                  *(uint32_t*)&h2, *(uint32_t*)&h3);
            uint4 vl = make_uint4(*(uint32_t*)&l0, *(uint32_t*)&l1,
                                  *(uint32_t*)&l2, *(uint32_t*)&l3);
            *(uint4*)(smn + (sB_hi - sb) + so + j * 16) = vh;
            *(uint4*)(smn + (sB_lo - sb) + so + j * 16) = vl;
        }
    };
    auto cpA = [&](int it) {
        if (it < NCHUNK_WC) {
            uint32_t so = (it & 1) * WC_STG;
            size_t ko = (size_t)it * 128;            // +64 h = +128B
            #pragma unroll
            for (int i = 0; i < 4; i++) {
                cp16(sAh + so + i * 16, gAh + ko + i * 16);
                cp16(sAl + so + i * 16, gAl + ko + i * 16);
            }
        }
        CP_COMMIT();
    };

    float acc[2][8][4];
    #pragma unroll
    for (int mb = 0; mb < 2; mb++)
        #pragma unroll
        for (int nf = 0; nf < 8; nf++)
            #pragma unroll
            for (int e = 0; e < 4; e++) acc[mb][nf][e] = 0.f;

    loadB(0); cpA(0);
    stsB(0);
    loadB(1); cpA(1);

    for (int it = 0; it < NCHUNK_WC; ++it) {
        uint32_t st = sb + (it & 1) * WC_STG;
        CP_WAIT1();
        __syncthreads();
        #pragma unroll
        for (int ks = 0; ks < 4; ks++) {
            uint32_t ah[2][4], al[2][4];
            #pragma unroll
            for (int mb = 0; mb < 2; mb++) {
                uint32_t r = (wm * 32 + mb * 16 + (lid & 15));
                uint32_t ad = st + r * PA + ks * 32 + (lid >> 4) * 16;
                ldsm4(ah[mb], ad + WC_AH);
                ldsm4(al[mb], ad + WC_AL);
            }
            #pragma unroll
            for (int nq = 0; nq < 4; nq++) {
                uint32_t r = ks * 16 + ((lid >> 3) & 1) * 8 + (lid & 7);
                uint32_t cb = (wn * 64 + nq * 16) * 2 + ((lid >> 4) & 1) * 16;
                uint32_t ad = st + r * PB + cb;
                uint32_t bh[4], bl[4];
                ldsm4t(bh, ad + WC_BH);
                ldsm4t(bl, ad + WC_BL);
                #pragma unroll
                for (int mb = 0; mb < 2; mb++)
                    #pragma unroll
                    for (int f = 0; f < 2; f++) {
                        mma16816(acc[mb][nq * 2 + f], ah[mb], &bh[f * 2]);
                        mma16816(acc[mb][nq * 2 + f], al[mb], &bh[f * 2]);
                        mma16816(acc[mb][nq * 2 + f], ah[mb], &bl[f * 2]);
                    }
            }
        }
        __syncthreads();
        if (it + 1 < NCHUNK_WC) stsB(((it + 1) & 1) * WC_STG);
        if (it + 2 < NCHUNK_WC) loadB(it + 2);
        cpA(it + 2);
    }

    // epilogue: split fp32 -> bf16 hi/lo, store [o][c]
    #pragma unroll
    for (int mb = 0; mb < 2; mb++)
        #pragma unroll
        for (int nf = 0; nf < 8; nf++) {
            int o = wm * 32 + mb * 16 + gid;
            int c = c0 + wn * 64 + nf * 8 + t4 * 2;
            #pragma unroll
            for (int half = 0; half < 2; half++) {
                __nv_bfloat162 hi, lo;
                split2(acc[mb][nf][half * 2 + 0], acc[mb][nf][half * 2 + 1], hi, lo);
                size_t idx = (size_t)(o + half * 8) * K_PAD + c;
                *(__nv_bfloat162*)(g_wchi + idx) = hi;
                *(__nv_bfloat162*)(g_wclo + idx) = lo;
            }
        }
}

// ---------------- kernel 5: main GEMM  out_part = hist @ Wc^T ------------
// CTA: 128 m x 128 n, K-slice 1280. grid (32, NSLICE). 8 warps (4m x 2n).
#define MG_A  0
#define MG_BH 18432
#define MG_BL 36864
#define MG_STG 55296

__global__ void __launch_bounds__(256, 2) main_gemm() {
    extern __shared__ char smn[];
    uint32_t sb = smem_u32(smn);
    const int tid = threadIdx.x, lid = tid & 31, wid = tid >> 5;
    const int wm = wid >> 1, wn = wid & 1, gid = lid >> 2, t4 = lid & 3;
    const int m0 = blockIdx.x * 128;
    const int kbase = blockIdx.y * K_SLICE;

    const int arow = tid >> 1;
    const int acol = (tid & 1) * 64;
    const char* gA  = (const char*)(g_hist + (size_t)(m0 + arow) * K_PAD + kbase) + acol;
    const char* gBh = (const char*)(g_wchi + (size_t)arow * K_PAD + kbase) + acol;
    const char* gBl = (const char*)(g_wclo + (size_t)arow * K_PAD + kbase) + acol;
    const uint32_t sA  = sb + MG_A  + arow * PA + acol;
    const uint32_t sBh = sb + MG_BH + arow * PA + acol;
    const uint32_t sBl = sb + MG_BL + arow * PA + acol;

    float acc[2][8][4];
    #pragma unroll
    for (int mb = 0; mb < 2; mb++)
        #pragma unroll
        for (int nf = 0; nf < 8; nf++)
            #pragma unroll
            for (int e = 0; e < 4; e++) acc[mb][nf][e] = 0.f;

    auto issue = [&](int it) {
        if (it < NCHUNK_MAIN) {
            uint32_t so = (it & 1) * MG_STG;
            size_t ko = (size_t)it * 128;
            #pragma unroll
            for (int i = 0; i < 4; i++) {
                cp16(sA  + so + i * 16, gA  + ko + i * 16);
                cp16(sBh + so + i * 16, gBh + ko + i * 16);
                cp16(sBl + so + i * 16, gBl + ko + i * 16);
            }
        }
        CP_COMMIT();
    };

    issue(0); issue(1);
    for (int it = 0; it < NCHUNK_MAIN; ++it) {
        uint32_t st = sb + (it & 1) * MG_STG;
        CP_WAIT1();
        __syncthreads();
        #pragma unroll
        for (int ks = 0; ks < 4; ks++) {
            uint32_t a[2][4];
            #pragma unroll
            for (int mb = 0; mb < 2; mb++) {
                uint32_t r = (wm * 32 + mb * 16 + (lid & 15));
                ldsm4(a[mb], st + MG_A + r * PA + ks * 32 + (lid >> 4) * 16);
            }
            #pragma unroll
            for (int nq = 0; nq < 4; nq++) {
                uint32_t r = wn * 64 + nq * 16 + ((lid >> 4) & 1) * 8 + (lid & 7);
                uint32_t ad = st + r * PA + ks * 32 + ((lid >> 3) & 1) * 16;
                uint32_t bh[4], bl[4];
                ldsm4(bh, ad + (MG_BH - MG_A));
                ldsm4(bl, ad + (MG_BL - MG_A));
                #pragma unroll
                for (int mb = 0; mb < 2; mb++)
                    #pragma unroll
                    for (int f = 0; f < 2; f++) {
                        mma16816(acc[mb][nq * 2 + f], a[mb], &bh[f * 2]);
                        mma16816(acc[mb][nq * 2 + f], a[mb], &bl[f * 2]);
                    }
            }
        }
        __syncthreads();
        issue(it + 2);
    }

    float* base = g_part + (size_t)blockIdx.y * BATCH * NPAD;
    #pragma unroll
    for (int mb = 0; mb < 2; mb++)
        #pragma unroll
        for (int nf = 0; nf < 8; nf++) {
            int row = m0 + wm * 32 + mb * 16 + gid;
            int col = wn * 64 + nf * 8 + t4 * 2;
            *(float2*)(base + (size_t)row * NPAD + col) =
                make_float2(acc[mb][nf][0], acc[mb][nf][1]);
            *(float2*)(base + (size_t)(row + 8) * NPAD + col) =
                make_float2(acc[mb][nf][2], acc[mb][nf][3]);
        }
}

// ---------------- kernel 6: split-K reduce + bias ------------------------
__global__ void __launch_bounds__(256) reduce_kernel(float* __restrict__ out) {
    int i = blockIdx.x * 256 + threadIdx.x;   // BATCH*OUTPUT threads exactly
    int b = i / OUTPUT;
    int o = i - b * OUTPUT;
    float s = g_bc[o];
    #pragma unroll
    for (int sl = 0; sl < NSLICE; sl++)
        s += g_part[((size_t)sl * BATCH + b) * NPAD + o];
    out[i] = s;
}

// ---------------- launch ---------------------------------------------------
extern "C" void kernel_launch(void* const* d_in, const int* in_sizes, int n_in,
                              void* d_out, int out_size) {
    const int*   words = (const int*)  d_in[0];
    const float* W1    = (const float*)d_in[1];
    const float* b1    = (const float*)d_in[2];
    const float* W2    = (const float*)d_in[3];
    const float* b2    = (const float*)d_in[4];

    hist_kernel<<<BATCH, 256>>>(words);
    conv_w2<<<(NPAD * HIDDEN) / 256, 256>>>(W2);
    bc_kernel<<<OUTPUT / 4, 128>>>(W2, b1, b2);

    cudaFuncSetAttribute(wc_gemm, cudaFuncAttributeMaxDynamicSharedMemorySize, 2 * WC_STG);
    wc_gemm<<<K_PAD / 128, 256, 2 * WC_STG>>>(W1);

    cudaFuncSetAttribute(main_gemm, cudaFuncAttributeMaxDynamicSharedMemorySize, 2 * MG_STG);
    main_gemm<<<dim3(32, NSLICE), 256, 2 * MG_STG>>>();

    reduce_kernel<<<(BATCH * OUTPUT) / 256, 256>>>((float*)d_out);
}

// round 4
// speedup vs baseline: 1.9902x; 1.3645x over previous
#include <cuda_runtime.h>
#include <cuda_bf16.h>
#include <cuda_fp16.h>
#include <cstdint>

#define CHARS   10000
#define HIDDEN  1024
#define OUTPUT  100
#define BATCH   4096
#define MAXLEN  2048

#define K_PAD   10240
#define NPAD    128
#define NSLICE  8
#define K_SLICE (K_PAD / NSLICE)      // 1280
#define NCHUNK_MAIN (K_SLICE / 64)    // 20
#define WC_KSLICE 512
#define NCHUNK_WC (WC_KSLICE / 64)    // 8

// ---------------- device scratch (static; allocations are banned) --------
__device__ __half         g_hist[(size_t)BATCH * K_PAD];    // 84 MB
__device__ __nv_bfloat16  g_w2h[(size_t)NPAD * HIDDEN];
__device__ __nv_bfloat16  g_w2l[(size_t)NPAD * HIDDEN];
__device__ float          g_wcp[2][(size_t)NPAD * K_PAD];   // 10.5 MB
__device__ __half         g_wcf[(size_t)NPAD * K_PAD];      // 2.6 MB
__device__ float          g_part[(size_t)NSLICE * BATCH * NPAD]; // 16.8 MB
__device__ float          g_bc[OUTPUT];

// ---------------- PTX helpers (portable sm_80-class only) ----------------
__device__ __forceinline__ uint32_t smem_u32(const void* p) {
    uint32_t a;
    asm("{ .reg .u64 t; cvta.to.shared.u64 t, %1; cvt.u32.u64 %0, t; }"
        : "=r"(a) : "l"(p));
    return a;
}

__device__ __forceinline__ void cp16(uint32_t s, const void* g) {
    asm volatile("cp.async.cg.shared.global [%0], [%1], 16;" :: "r"(s), "l"(g));
}
#define CP_COMMIT() asm volatile("cp.async.commit_group;" ::: "memory")
#define CP_WAIT1()  asm volatile("cp.async.wait_group 1;"  ::: "memory")

__device__ __forceinline__ void ldsm4(uint32_t* r, uint32_t a) {
    asm volatile("ldmatrix.sync.aligned.m8n8.x4.shared.b16 {%0,%1,%2,%3}, [%4];"
        : "=r"(r[0]), "=r"(r[1]), "=r"(r[2]), "=r"(r[3]) : "r"(a));
}
__device__ __forceinline__ void ldsm4t(uint32_t* r, uint32_t a) {
    asm volatile("ldmatrix.sync.aligned.m8n8.x4.trans.shared.b16 {%0,%1,%2,%3}, [%4];"
        : "=r"(r[0]), "=r"(r[1]), "=r"(r[2]), "=r"(r[3]) : "r"(a));
}

// D(16x8,f32) += A(16x16,bf16) @ B(16x8,bf16)
__device__ __forceinline__ void mma_bf16(float* c, const uint32_t* a, const uint32_t* b) {
    asm volatile(
        "mma.sync.aligned.m16n8k16.row.col.f32.bf16.bf16.f32 "
        "{%0,%1,%2,%3}, {%4,%5,%6,%7}, {%8,%9}, {%0,%1,%2,%3};"
        : "+f"(c[0]), "+f"(c[1]), "+f"(c[2]), "+f"(c[3])
        : "r"(a[0]), "r"(a[1]), "r"(a[2]), "r"(a[3]), "r"(b[0]), "r"(b[1]));
}
// D(16x8,f32) += A(16x16,f16) @ B(16x8,f16)
__device__ __forceinline__ void mma_f16(float* c, const uint32_t* a, const uint32_t* b) {
    asm volatile(
        "mma.sync.aligned.m16n8k16.row.col.f32.f16.f16.f32 "
        "{%0,%1,%2,%3}, {%4,%5,%6,%7}, {%8,%9}, {%0,%1,%2,%3};"
        : "+f"(c[0]), "+f"(c[1]), "+f"(c[2]), "+f"(c[3])
        : "r"(a[0]), "r"(a[1]), "r"(a[2]), "r"(a[3]), "r"(b[0]), "r"(b[1]));
}

__device__ __forceinline__ void split2(float a, float b,
                                       __nv_bfloat162& hi, __nv_bfloat162& lo) {
    __nv_bfloat16 h0 = __float2bfloat16_rn(a);
    __nv_bfloat16 h1 = __float2bfloat16_rn(b);
    hi = __nv_bfloat162(h0, h1);
    lo = __nv_bfloat162(__float2bfloat16_rn(a - __bfloat162float(h0)),
                        __float2bfloat16_rn(b - __bfloat162float(h1)));
}

// smem pitch (bytes) for 64-col 16-bit rows, +8 elem pad
#define PA 144

// ---------------- kernel 1: per-row histogram -> fp16 (exact) ------------
__global__ void __launch_bounds__(256) hist_kernel(const int* __restrict__ words) {
    __shared__ unsigned cnt[K_PAD / 2];
    int b = blockIdx.x;
    for (int i = threadIdx.x; i < K_PAD / 2; i += 256) cnt[i] = 0u;
    __syncthreads();
    const int* w = words + (size_t)b * MAXLEN;
    #pragma unroll 8
    for (int j = threadIdx.x; j < MAXLEN; j += 256) {
        unsigned c = (unsigned)w[j];
        atomicAdd(&cnt[c >> 1], 1u << ((c & 1u) * 16));
    }
    __syncthreads();
    __half2* out = (__half2*)(g_hist + (size_t)b * K_PAD);
    for (int i = threadIdx.x; i < K_PAD / 2; i += 256) {
        unsigned v = cnt[i];
        out[i] = __floats2half2_rn((float)(v & 0xFFFFu), (float)(v >> 16));
    }
}

// ---------------- kernel 2: split W2 -> bf16 hi/lo, padded [128][1024] ---
__global__ void __launch_bounds__(256) conv_w2(const float* __restrict__ W2) {
    unsigned i = blockIdx.x * 256u + threadIdx.x;
    unsigned o = i >> 10;
    float v = (o < OUTPUT) ? W2[(size_t)o * HIDDEN + (i & 1023u)] : 0.f;
    __nv_bfloat16 hi = __float2bfloat16_rn(v);
    g_w2h[i] = hi;
    g_w2l[i] = __float2bfloat16_rn(v - __bfloat162float(hi));
}

// ---------------- kernel 3: bc = b2 + W2 @ b1 (100 warps) -----------------
__global__ void __launch_bounds__(128) bc_kernel(const float* __restrict__ W2,
                                                 const float* __restrict__ b1,
                                                 const float* __restrict__ b2) {
    int o = blockIdx.x * 4 + (threadIdx.x >> 5);
    int lane = threadIdx.x & 31;
    const float* w = W2 + (size_t)o * HIDDEN;
    float s = 0.f;
    #pragma unroll 8
    for (int h = lane; h < HIDDEN; h += 32) s += w[h] * b1[h];
    #pragma unroll
    for (int off = 16; off; off >>= 1) s += __shfl_xor_sync(0xFFFFFFFFu, s, off);
    if (lane == 0) g_bc[o] = b2[o] + s;
}

// ---------------- kernel 4: Wc partials = W2 @ W1 (3-pass bf16 HMMA) -----
// CTA tile: 128 o x 64 c, K-slice 512 h (grid.y=2). grid (160, 2) = 320 CTAs.
// 8 warps (4m x 2n), warp tile 32o x 32c. A=W2 hi/lo cp.async; B=W1 fp32 LDG
// -> reg split -> STS. smem stage 55296 B, 2 stages -> 2 CTAs/SM.
#define WC_AH 0
#define WC_AL 18432
#define WC_BH 36864
#define WC_BL 46080
#define WC_STG 55296

__global__ void __launch_bounds__(256, 2) wc_gemm(const float* __restrict__ W1) {
    extern __shared__ char smn[];
    uint32_t sb = smem_u32(smn);
    const int tid = threadIdx.x, lid = tid & 31, wid = tid >> 5;
    const int wm = wid >> 1, wn = wid & 1, gid = lid >> 2, t4 = lid & 3;
    const int c0 = blockIdx.x * 64;
    const int kbase = blockIdx.y * WC_KSLICE;

    // A (W2 hi/lo): 128 rows x 128B per chunk
    const int arow = tid >> 1;
    const int acol = (tid & 1) * 64;
    const char* gAh = (const char*)(g_w2h + (size_t)arow * HIDDEN + kbase) + acol;
    const char* gAl = (const char*)(g_w2l + (size_t)arow * HIDDEN + kbase) + acol;
    const uint32_t sAh = sb + WC_AH + arow * PA + acol;
    const uint32_t sAl = sb + WC_AL + arow * PA + acol;

    // B (W1 fp32): 64 h-rows x 64 c per chunk; thread: row=tid>>2, 16 floats
    const int brow = tid >> 2;
    const int bcole = (tid & 3) * 16;
    const uint32_t oB_hi = WC_BH + brow * PA + bcole * 2;
    const uint32_t oB_lo = WC_BL + brow * PA + bcole * 2;

    float4 rb[4];
    auto loadB = [&](int it) {
        const float* p = W1 + (size_t)(kbase + it * 64 + brow) * CHARS + c0 + bcole;
        #pragma unroll
        for (int i = 0; i < 4; i++) {
            int c = c0 + bcole + i * 4;
            rb[i] = (c < CHARS) ? *(const float4*)(p + i * 4)
                                : make_float4(0.f, 0.f, 0.f, 0.f);
        }
    };
    auto stsB = [&](uint32_t so) {
        #pragma unroll
        for (int j = 0; j < 2; j++) {
            __nv_bfloat162 h0, l0, h1, l1, h2, l2, h3, l3;
            split2(rb[2*j].x,   rb[2*j].y,   h0, l0);
            split2(rb[2*j].z,   rb[2*j].w,   h1, l1);
            split2(rb[2*j+1].x, rb[2*j+1].y, h2, l2);
            split2(rb[2*j+1].z, rb[2*j+1].w, h3, l3);
            *(uint4*)(smn + oB_hi + so + j * 16) =
                make_uint4(*(uint32_t*)&h0, *(uint32_t*)&h1,
                           *(uint32_t*)&h2, *(uint32_t*)&h3);
            *(uint4*)(smn + oB_lo + so + j * 16) =
                make_uint4(*(uint32_t*)&l0, *(uint32_t*)&l1,
                           *(uint32_t*)&l2, *(uint32_t*)&l3);
        }
    };
    auto cpA = [&](int it) {
        if (it < NCHUNK_WC) {
            uint32_t so = (it & 1) * WC_STG;
            size_t ko = (size_t)it * 128;
            #pragma unroll
            for (int i = 0; i < 4; i++) {
                cp16(sAh + so + i * 16, gAh + ko + i * 16);
                cp16(sAl + so + i * 16, gAl + ko + i * 16);
            }
        }
        CP_COMMIT();
    };

    float acc[2][4][4];
    #pragma unroll
    for (int mb = 0; mb < 2; mb++)
        #pragma unroll
        for (int nf = 0; nf < 4; nf++)
            #pragma unroll
            for (int e = 0; e < 4; e++) acc[mb][nf][e] = 0.f;

    loadB(0); cpA(0);
    stsB(0);
    loadB(1); cpA(1);

    for (int it = 0; it < NCHUNK_WC; ++it) {
        uint32_t st = sb + (it & 1) * WC_STG;
        CP_WAIT1();
        __syncthreads();
        #pragma unroll
        for (int ks = 0; ks < 4; ks++) {
            uint32_t ah[2][4], al[2][4];
            #pragma unroll
            for (int mb = 0; mb < 2; mb++) {
                uint32_t r = (wm * 32 + mb * 16 + (lid & 15));
                uint32_t ad = st + r * PA + ks * 32 + (lid >> 4) * 16;
                ldsm4(ah[mb], ad + WC_AH);
                ldsm4(al[mb], ad + WC_AL);
            }
            #pragma unroll
            for (int nq = 0; nq < 2; nq++) {
                uint32_t r = ks * 16 + ((lid >> 3) & 1) * 8 + (lid & 7);
                uint32_t cb = (wn * 32 + nq * 16) * 2 + ((lid >> 4) & 1) * 16;
                uint32_t ad = st + r * PA + cb;
                uint32_t bh[4], bl[4];
                ldsm4t(bh, ad + WC_BH);
                ldsm4t(bl, ad + WC_BL);
                #pragma unroll
                for (int mb = 0; mb < 2; mb++)
                    #pragma unroll
                    for (int f = 0; f < 2; f++) {
                        mma_bf16(acc[mb][nq * 2 + f], ah[mb], &bh[f * 2]);
                        mma_bf16(acc[mb][nq * 2 + f], al[mb], &bh[f * 2]);
                        mma_bf16(acc[mb][nq * 2 + f], ah[mb], &bl[f * 2]);
                    }
            }
        }
        __syncthreads();
        if (it + 1 < NCHUNK_WC) stsB(((it + 1) & 1) * WC_STG);
        if (it + 2 < NCHUNK_WC) loadB(it + 2);
        cpA(it + 2);
    }

    float* base = g_wcp[blockIdx.y];
    #pragma unroll
    for (int mb = 0; mb < 2; mb++)
        #pragma unroll
        for (int nf = 0; nf < 4; nf++) {
            int o = wm * 32 + mb * 16 + gid;
            int c = c0 + wn * 32 + nf * 8 + t4 * 2;
            *(float2*)(base + (size_t)o * K_PAD + c) =
                make_float2(acc[mb][nf][0], acc[mb][nf][1]);
            *(float2*)(base + (size_t)(o + 8) * K_PAD + c) =
                make_float2(acc[mb][nf][2], acc[mb][nf][3]);
        }
}

// ---------------- kernel 4b: combine slices -> fp16 Wc --------------------
__global__ void __launch_bounds__(256) wc_combine() {
    unsigned i = blockIdx.x * 256u + threadIdx.x;   // over NPAD*K_PAD/2
    float2 a = ((const float2*)g_wcp[0])[i];
    float2 b = ((const float2*)g_wcp[1])[i];
    ((__half2*)g_wcf)[i] = __floats2half2_rn(a.x + b.x, a.y + b.y);
}

// ---------------- kernel 5: main GEMM  part = hist @ Wc^T (fp16, 1 pass) --
// CTA: 128 m x 128 n, K-slice 1280. grid (32, 8). 8 warps (4m x 2n).
#define MG_A  0
#define MG_B  18432
#define MG_STG 36864

__global__ void __launch_bounds__(256, 2) main_gemm() {
    extern __shared__ char smn[];
    uint32_t sb = smem_u32(smn);
    const int tid = threadIdx.x, lid = tid & 31, wid = tid >> 5;
    const int wm = wid >> 1, wn = wid & 1, gid = lid >> 2, t4 = lid & 3;
    const int m0 = blockIdx.x * 128;
    const int kbase = blockIdx.y * K_SLICE;

    const int arow = tid >> 1;
    const int acol = (tid & 1) * 64;
    const char* gA = (const char*)(g_hist + (size_t)(m0 + arow) * K_PAD + kbase) + acol;
    const char* gB = (const char*)(g_wcf  + (size_t)arow * K_PAD + kbase) + acol;
    const uint32_t sA = sb + MG_A + arow * PA + acol;
    const uint32_t sB = sb + MG_B + arow * PA + acol;

    float acc[2][8][4];
    #pragma unroll
    for (int mb = 0; mb < 2; mb++)
        #pragma unroll
        for (int nf = 0; nf < 8; nf++)
            #pragma unroll
            for (int e = 0; e < 4; e++) acc[mb][nf][e] = 0.f;

    auto issue = [&](int it) {
        if (it < NCHUNK_MAIN) {
            uint32_t so = (it & 1) * MG_STG;
            size_t ko = (size_t)it * 128;
            #pragma unroll
            for (int i = 0; i < 4; i++) {
                cp16(sA + so + i * 16, gA + ko + i * 16);
                cp16(sB + so + i * 16, gB + ko + i * 16);
            }
        }
        CP_COMMIT();
    };

    issue(0); issue(1);
    for (int it = 0; it < NCHUNK_MAIN; ++it) {
        uint32_t st = sb + (it & 1) * MG_STG;
        CP_WAIT1();
        __syncthreads();
        #pragma unroll
        for (int ks = 0; ks < 4; ks++) {
            uint32_t a[2][4];
            #pragma unroll
            for (int mb = 0; mb < 2; mb++) {
                uint32_t r = (wm * 32 + mb * 16 + (lid & 15));
                ldsm4(a[mb], st + MG_A + r * PA + ks * 32 + (lid >> 4) * 16);
            }
            #pragma unroll
            for (int nq = 0; nq < 4; nq++) {
                uint32_t r = wn * 64 + nq * 16 + ((lid >> 4) & 1) * 8 + (lid & 7);
                uint32_t ad = st + r * PA + ks * 32 + ((lid >> 3) & 1) * 16;
                uint32_t bh[4];
                ldsm4(bh, ad + (MG_B - MG_A));
                #pragma unroll
                for (int mb = 0; mb < 2; mb++)
                    #pragma unroll
                    for (int f = 0; f < 2; f++)
                        mma_f16(acc[mb][nq * 2 + f], a[mb], &bh[f * 2]);
            }
        }
        __syncthreads();
        issue(it + 2);
    }

    float* base = g_part + (size_t)blockIdx.y * BATCH * NPAD;
    #pragma unroll
    for (int mb = 0; mb < 2; mb++)
        #pragma unroll
        for (int nf = 0; nf < 8; nf++) {
            int row = m0 + wm * 32 + mb * 16 + gid;
            int col = wn * 64 + nf * 8 + t4 * 2;
            *(float2*)(base + (size_t)row * NPAD + col) =
                make_float2(acc[mb][nf][0], acc[mb][nf][1]);
            *(float2*)(base + (size_t)(row + 8) * NPAD + col) =
                make_float2(acc[mb][nf][2], acc[mb][nf][3]);
        }
}

// ---------------- kernel 6: split-K reduce + bias ------------------------
__global__ void __launch_bounds__(256) reduce_kernel(float* __restrict__ out) {
    int i = blockIdx.x * 256 + threadIdx.x;
    int b = i / OUTPUT;
    int o = i - b * OUTPUT;
    float s = g_bc[o];
    #pragma unroll
    for (int sl = 0; sl < NSLICE; sl++)
        s += g_part[((size_t)sl * BATCH + b) * NPAD + o];
    out[i] = s;
}

// ---------------- launch ---------------------------------------------------
extern "C" void kernel_launch(void* const* d_in, const int* in_sizes, int n_in,
                              void* d_out, int out_size) {
    const int*   words = (const int*)  d_in[0];
    const float* W1    = (const float*)d_in[1];
    const float* b1    = (const float*)d_in[2];
    const float* W2    = (const float*)d_in[3];
    const float* b2    = (const float*)d_in[4];

    hist_kernel<<<BATCH, 256>>>(words);
    conv_w2<<<(NPAD * HIDDEN) / 256, 256>>>(W2);
    bc_kernel<<<OUTPUT / 4, 128>>>(W2, b1, b2);

    cudaFuncSetAttribute(wc_gemm, cudaFuncAttributeMaxDynamicSharedMemorySize, 2 * WC_STG);
    wc_gemm<<<dim3(K_PAD / 64, 2), 256, 2 * WC_STG>>>(W1);
    wc_combine<<<(NPAD * K_PAD / 2) / 256, 256>>>();

    cudaFuncSetAttribute(main_gemm, cudaFuncAttributeMaxDynamicSharedMemorySize, 2 * MG_STG);
    main_gemm<<<dim3(32, NSLICE), 256, 2 * MG_STG>>>();

    reduce_kernel<<<(BATCH * OUTPUT) / 256, 256>>>((float*)d_out);
}

// round 5
// speedup vs baseline: 2.3181x; 1.1648x over previous
#include <cuda_runtime.h>
#include <cuda_bf16.h>
#include <cuda_fp16.h>
#include <cstdint>

#define CHARS   10000
#define HIDDEN  1024
#define OUTPUT  100
#define BATCH   4096
#define MAXLEN  2048

#define K_PAD   10240
#define NPAD    128
#define NSLICE  8
#define K_SLICE (K_PAD / NSLICE)      // 1280
#define NCHUNK_MAIN (K_SLICE / 64)    // 20
#define WC_KSLICE 512
#define NCHUNK_WC (WC_KSLICE / 64)    // 8

// ---------------- device scratch (static; allocations are banned) --------
__device__ __half  g_hist[(size_t)BATCH * K_PAD];           // 84 MB
__device__ __half  g_w2f[(size_t)NPAD * HIDDEN];            // 256 KB
__device__ float   g_wcp[2][(size_t)NPAD * K_PAD];          // 10.5 MB
__device__ __half  g_wcf[(size_t)NPAD * K_PAD];             // 2.6 MB
__device__ float   g_part[(size_t)NSLICE * BATCH * NPAD];   // 16.8 MB
__device__ float   g_bc[OUTPUT];

// ---------------- PTX helpers (portable sm_80-class only) ----------------
__device__ __forceinline__ uint32_t smem_u32(const void* p) {
    uint32_t a;
    asm("{ .reg .u64 t; cvta.to.shared.u64 t, %1; cvt.u32.u64 %0, t; }"
        : "=r"(a) : "l"(p));
    return a;
}

__device__ __forceinline__ void cp16(uint32_t s, const void* g) {
    asm volatile("cp.async.cg.shared.global [%0], [%1], 16;" :: "r"(s), "l"(g));
}
#define CP_COMMIT() asm volatile("cp.async.commit_group;" ::: "memory")
#define CP_WAIT1()  asm volatile("cp.async.wait_group 1;"  ::: "memory")
#define CP_WAIT2()  asm volatile("cp.async.wait_group 2;"  ::: "memory")

__device__ __forceinline__ void ldsm4(uint32_t* r, uint32_t a) {
    asm volatile("ldmatrix.sync.aligned.m8n8.x4.shared.b16 {%0,%1,%2,%3}, [%4];"
        : "=r"(r[0]), "=r"(r[1]), "=r"(r[2]), "=r"(r[3]) : "r"(a));
}
__device__ __forceinline__ void ldsm4t(uint32_t* r, uint32_t a) {
    asm volatile("ldmatrix.sync.aligned.m8n8.x4.trans.shared.b16 {%0,%1,%2,%3}, [%4];"
        : "=r"(r[0]), "=r"(r[1]), "=r"(r[2]), "=r"(r[3]) : "r"(a));
}

// D(16x8,f32) += A(16x16,f16) @ B(16x8,f16)
__device__ __forceinline__ void mma_f16(float* c, const uint32_t* a, const uint32_t* b) {
    asm volatile(
        "mma.sync.aligned.m16n8k16.row.col.f32.f16.f16.f32 "
        "{%0,%1,%2,%3}, {%4,%5,%6,%7}, {%8,%9}, {%0,%1,%2,%3};"
        : "+f"(c[0]), "+f"(c[1]), "+f"(c[2]), "+f"(c[3])
        : "r"(a[0]), "r"(a[1]), "r"(a[2]), "r"(a[3]), "r"(b[0]), "r"(b[1]));
}

// smem pitch (bytes) for 64-col 16-bit rows, +8 elem pad
#define PA 144

// ---------------- kernel 1: per-row histogram -> fp16 (exact) ------------
__global__ void __launch_bounds__(256) hist_kernel(const int* __restrict__ words) {
    __shared__ unsigned cnt[K_PAD / 2];
    int b = blockIdx.x;
    for (int i = threadIdx.x; i < K_PAD / 2; i += 256) cnt[i] = 0u;
    __syncthreads();
    const int* w = words + (size_t)b * MAXLEN;
    #pragma unroll 8
    for (int j = threadIdx.x; j < MAXLEN; j += 256) {
        unsigned c = (unsigned)w[j];
        atomicAdd(&cnt[c >> 1], 1u << ((c & 1u) * 16));
    }
    __syncthreads();
    __half2* out = (__half2*)(g_hist + (size_t)b * K_PAD);
    for (int i = threadIdx.x; i < K_PAD / 2; i += 256) {
        unsigned v = cnt[i];
        out[i] = __floats2half2_rn((float)(v & 0xFFFFu), (float)(v >> 16));
    }
}

// ---------------- kernel 2: W2 -> fp16, padded [128][1024] ---------------
__global__ void __launch_bounds__(256) conv_w2(const float* __restrict__ W2) {
    unsigned i = blockIdx.x * 256u + threadIdx.x;
    unsigned o = i >> 10;
    float v = (o < OUTPUT) ? W2[(size_t)o * HIDDEN + (i & 1023u)] : 0.f;
    g_w2f[i] = __float2half_rn(v);
}

// ---------------- kernel 3: bc = b2 + W2 @ b1 (100 warps) -----------------
__global__ void __launch_bounds__(128) bc_kernel(const float* __restrict__ W2,
                                                 const float* __restrict__ b1,
                                                 const float* __restrict__ b2) {
    int o = blockIdx.x * 4 + (threadIdx.x >> 5);
    int lane = threadIdx.x & 31;
    const float* w = W2 + (size_t)o * HIDDEN;
    float s = 0.f;
    #pragma unroll 8
    for (int h = lane; h < HIDDEN; h += 32) s += w[h] * b1[h];
    #pragma unroll
    for (int off = 16; off; off >>= 1) s += __shfl_xor_sync(0xFFFFFFFFu, s, off);
    if (lane == 0) g_bc[o] = b2[o] + s;
}

// ---------------- kernel 4: Wc partials = W2 @ W1 (fp16 single-pass) -----
// CTA tile: 128 o x 64 c, K-slice 512 h. grid (160, 2) = 320 CTAs.
// 8 warps (4m x 2n). A = W2 fp16 cp.async; B = W1 fp32 LDG -> fp16 -> STS.
// stage = 27648 B, 2 stages -> 3 CTAs/SM.
#define WC_A 0
#define WC_B 18432
#define WC_STG 27648

__global__ void __launch_bounds__(256, 3) wc_gemm(const float* __restrict__ W1) {
    extern __shared__ char smn[];
    uint32_t sb = smem_u32(smn);
    const int tid = threadIdx.x, lid = tid & 31, wid = tid >> 5;
    const int wm = wid >> 1, wn = wid & 1, gid = lid >> 2, t4 = lid & 3;
    const int c0 = blockIdx.x * 64;
    const int kbase = blockIdx.y * WC_KSLICE;

    // A (W2 fp16): 128 rows x 128B per chunk
    const int arow = tid >> 1;
    const int acol = (tid & 1) * 64;
    const char* gA = (const char*)(g_w2f + (size_t)arow * HIDDEN + kbase) + acol;
    const uint32_t sA = sb + WC_A + arow * PA + acol;

    // B (W1 fp32): 64 h-rows x 64 c per chunk; thread: row=tid>>2, 16 floats
    const int brow = tid >> 2;
    const int bcole = (tid & 3) * 16;
    const uint32_t oB = WC_B + brow * PA + bcole * 2;

    float4 rb[4];
    auto loadB = [&](int it) {
        const float* p = W1 + (size_t)(kbase + it * 64 + brow) * CHARS + c0 + bcole;
        #pragma unroll
        for (int i = 0; i < 4; i++) {
            int c = c0 + bcole + i * 4;
            rb[i] = (c < CHARS) ? *(const float4*)(p + i * 4)
                                : make_float4(0.f, 0.f, 0.f, 0.f);
        }
    };
    auto stsB = [&](uint32_t so) {
        #pragma unroll
        for (int j = 0; j < 2; j++) {
            __half2 h0 = __floats2half2_rn(rb[2*j].x,   rb[2*j].y);
            __half2 h1 = __floats2half2_rn(rb[2*j].z,   rb[2*j].w);
            __half2 h2 = __floats2half2_rn(rb[2*j+1].x, rb[2*j+1].y);
            __half2 h3 = __floats2half2_rn(rb[2*j+1].z, rb[2*j+1].w);
            *(uint4*)(smn + oB + so + j * 16) =
                make_uint4(*(uint32_t*)&h0, *(uint32_t*)&h1,
                           *(uint32_t*)&h2, *(uint32_t*)&h3);
        }
    };
    auto cpA = [&](int it) {
        if (it < NCHUNK_WC) {
            uint32_t so = (it & 1) * WC_STG;
            size_t ko = (size_t)it * 128;
            #pragma unroll
            for (int i = 0; i < 4; i++)
                cp16(sA + so + i * 16, gA + ko + i * 16);
        }
        CP_COMMIT();
    };

    float acc[2][4][4];
    #pragma unroll
    for (int mb = 0; mb < 2; mb++)
        #pragma unroll
        for (int nf = 0; nf < 4; nf++)
            #pragma unroll
            for (int e = 0; e < 4; e++) acc[mb][nf][e] = 0.f;

    loadB(0); cpA(0);
    stsB(0);
    loadB(1); cpA(1);

    for (int it = 0; it < NCHUNK_WC; ++it) {
        uint32_t st = sb + (it & 1) * WC_STG;
        CP_WAIT1();
        __syncthreads();
        #pragma unroll
        for (int ks = 0; ks < 4; ks++) {
            uint32_t a[2][4];
            #pragma unroll
            for (int mb = 0; mb < 2; mb++) {
                uint32_t r = (wm * 32 + mb * 16 + (lid & 15));
                ldsm4(a[mb], st + WC_A + r * PA + ks * 32 + (lid >> 4) * 16);
            }
            #pragma unroll
            for (int nq = 0; nq < 2; nq++) {
                uint32_t r = ks * 16 + ((lid >> 3) & 1) * 8 + (lid & 7);
                uint32_t cb = (wn * 32 + nq * 16) * 2 + ((lid >> 4) & 1) * 16;
                uint32_t b[4];
                ldsm4t(b, st + WC_B + r * PA + cb);
                #pragma unroll
                for (int mb = 0; mb < 2; mb++)
                    #pragma unroll
                    for (int f = 0; f < 2; f++)
                        mma_f16(acc[mb][nq * 2 + f], a[mb], &b[f * 2]);
            }
        }
        __syncthreads();
        if (it + 1 < NCHUNK_WC) stsB(((it + 1) & 1) * WC_STG);
        if (it + 2 < NCHUNK_WC) loadB(it + 2);
        cpA(it + 2);
    }

    float* base = g_wcp[blockIdx.y];
    #pragma unroll
    for (int mb = 0; mb < 2; mb++)
        #pragma unroll
        for (int nf = 0; nf < 4; nf++) {
            int o = wm * 32 + mb * 16 + gid;
            int c = c0 + wn * 32 + nf * 8 + t4 * 2;
            *(float2*)(base + (size_t)o * K_PAD + c) =
                make_float2(acc[mb][nf][0], acc[mb][nf][1]);
            *(float2*)(base + (size_t)(o + 8) * K_PAD + c) =
                make_float2(acc[mb][nf][2], acc[mb][nf][3]);
        }
}

// ---------------- kernel 4b: combine slices -> fp16 Wc --------------------
__global__ void __launch_bounds__(256) wc_combine() {
    unsigned i = blockIdx.x * 256u + threadIdx.x;   // over NPAD*K_PAD/2
    float2 a = ((const float2*)g_wcp[0])[i];
    float2 b = ((const float2*)g_wcp[1])[i];
    ((__half2*)g_wcf)[i] = __floats2half2_rn(a.x + b.x, a.y + b.y);
}

// ---------------- kernel 5: main GEMM  part = hist @ Wc^T (fp16) ---------
// CTA: 128 m x 128 n, K-slice 1280. grid (32, 8). 8 warps (4m x 2n).
// 3-stage cp.async pipeline.
#define MG_A  0
#define MG_B  18432
#define MG_STG 36864

__global__ void __launch_bounds__(256, 2) main_gemm() {
    extern __shared__ char smn[];
    uint32_t sb = smem_u32(smn);
    const int tid = threadIdx.x, lid = tid & 31, wid = tid >> 5;
    const int wm = wid >> 1, wn = wid & 1, gid = lid >> 2, t4 = lid & 3;
    const int m0 = blockIdx.x * 128;
    const int kbase = blockIdx.y * K_SLICE;

    const int arow = tid >> 1;
    const int acol = (tid & 1) * 64;
    const char* gA = (const char*)(g_hist + (size_t)(m0 + arow) * K_PAD + kbase) + acol;
    const char* gB = (const char*)(g_wcf  + (size_t)arow * K_PAD + kbase) + acol;
    const uint32_t sA = sb + MG_A + arow * PA + acol;
    const uint32_t sB = sb + MG_B + arow * PA + acol;

    float acc[2][8][4];
    #pragma unroll
    for (int mb = 0; mb < 2; mb++)
        #pragma unroll
        for (int nf = 0; nf < 8; nf++)
            #pragma unroll
            for (int e = 0; e < 4; e++) acc[mb][nf][e] = 0.f;

    auto issue = [&](int it, int sidx) {
        if (it < NCHUNK_MAIN) {
            uint32_t so = sidx * MG_STG;
            size_t ko = (size_t)it * 128;
            #pragma unroll
            for (int i = 0; i < 4; i++) {
                cp16(sA + so + i * 16, gA + ko + i * 16);
                cp16(sB + so + i * 16, gB + ko + i * 16);
            }
        }
        CP_COMMIT();
    };

    issue(0, 0); issue(1, 1); issue(2, 2);
    int sc = 0;            // stage of current iteration
    int sn = 0;            // stage for issue (it+3)
    for (int it = 0; it < NCHUNK_MAIN; ++it) {
        uint32_t st = sb + sc * MG_STG;
        CP_WAIT2();
        __syncthreads();
        #pragma unroll
        for (int ks = 0; ks < 4; ks++) {
            uint32_t a[2][4];
            #pragma unroll
            for (int mb = 0; mb < 2; mb++) {
                uint32_t r = (wm * 32 + mb * 16 + (lid & 15));
                ldsm4(a[mb], st + MG_A + r * PA + ks * 32 + (lid >> 4) * 16);
            }
            #pragma unroll
            for (int nq = 0; nq < 4; nq++) {
                uint32_t r = wn * 64 + nq * 16 + ((lid >> 4) & 1) * 8 + (lid & 7);
                uint32_t ad = st + r * PA + ks * 32 + ((lid >> 3) & 1) * 16;
                uint32_t bh[4];
                ldsm4(bh, ad + (MG_B - MG_A));
                #pragma unroll
                for (int mb = 0; mb < 2; mb++)
                    #pragma unroll
                    for (int f = 0; f < 2; f++)
                        mma_f16(acc[mb][nq * 2 + f], a[mb], &bh[f * 2]);
            }
        }
        __syncthreads();
        issue(it + 3, sn);
        sc = (sc == 2) ? 0 : sc + 1;
        sn = (sn == 2) ? 0 : sn + 1;
    }

    float* base = g_part + (size_t)blockIdx.y * BATCH * NPAD;
    #pragma unroll
    for (int mb = 0; mb < 2; mb++)
        #pragma unroll
        for (int nf = 0; nf < 8; nf++) {
            int row = m0 + wm * 32 + mb * 16 + gid;
            int col = wn * 64 + nf * 8 + t4 * 2;
            *(float2*)(base + (size_t)row * NPAD + col) =
                make_float2(acc[mb][nf][0], acc[mb][nf][1]);
            *(float2*)(base + (size_t)(row + 8) * NPAD + col) =
                make_float2(acc[mb][nf][2], acc[mb][nf][3]);
        }
}

// ---------------- kernel 6: split-K reduce + bias ------------------------
__global__ void __launch_bounds__(256) reduce_kernel(float* __restrict__ out) {
    int i = blockIdx.x * 256 + threadIdx.x;
    int b = i / OUTPUT;
    int o = i - b * OUTPUT;
    float s = g_bc[o];
    #pragma unroll
    for (int sl = 0; sl < NSLICE; sl++)
        s += g_part[((size_t)sl * BATCH + b) * NPAD + o];
    out[i] = s;
}

// ---------------- launch ---------------------------------------------------
extern "C" void kernel_launch(void* const* d_in, const int* in_sizes, int n_in,
                              void* d_out, int out_size) {
    const int*   words = (const int*)  d_in[0];
    const float* W1    = (const float*)d_in[1];
    const float* b1    = (const float*)d_in[2];
    const float* W2    = (const float*)d_in[3];
    const float* b2    = (const float*)d_in[4];

    hist_kernel<<<BATCH, 256>>>(words);
    conv_w2<<<(NPAD * HIDDEN) / 256, 256>>>(W2);
    bc_kernel<<<OUTPUT / 4, 128>>>(W2, b1, b2);

    cudaFuncSetAttribute(wc_gemm, cudaFuncAttributeMaxDynamicSharedMemorySize, 2 * WC_STG);
    wc_gemm<<<dim3(K_PAD / 64, 2), 256, 2 * WC_STG>>>(W1);
    wc_combine<<<(NPAD * K_PAD / 2) / 256, 256>>>();

    cudaFuncSetAttribute(main_gemm, cudaFuncAttributeMaxDynamicSharedMemorySize, 3 * MG_STG);
    main_gemm<<<dim3(32, NSLICE), 256, 3 * MG_STG>>>();

    reduce_kernel<<<(BATCH * OUTPUT) / 256, 256>>>((float*)d_out);
}